// round 10
// baseline (speedup 1.0000x reference)
#include <cuda_runtime.h>
#include <cuda_fp16.h>
#include <stdint.h>

// ============================================================================
// CrossAttention collapses algebraically:
//   softmax over k sums to 1 per query -> sum over (q,k) of scores = L = 2048.
//   einsum 'bvhd,bhqk->bvhd' has no shared contraction index, so attn = v*2048:
//     out = 2048 * x @ (Wv@Wo) + (2048 * bv@Wo + bo)
// encoder_x / Wq / bq / Wk / bk are dead inputs.
//
// R10: gemm2 latency-bound fix WITHOUT reg caps (R9's cap caused spills):
//   - warp tile 32x32 (32 accums) -> ~100 regs -> 2 CTAs/SM = 4 warps/SMSP.
//   - fp32 A-tile swizzle moved to 16B granularity -> conflict-free LDS.64
//     fragment reads (R8's 32B-granule version was 2-way conflicted).
// gemm1 (64x64, 272 CTAs, fused bias) kept from R9.
// ============================================================================

// ---------------- scratch ----------------------------------------------------
__device__ __half g_WcTh[1024u * 1024u];
__device__ float  g_t[1024];

// ---------------- helpers ----------------------------------------------------
__device__ __forceinline__ uint32_t smem_u32(const void* p) {
    uint32_t a;
    asm("{ .reg .u64 t; cvta.to.shared.u64 t, %1; cvt.u32.u64 %0, t; }"
        : "=r"(a) : "l"(p));
    return a;
}
__device__ __forceinline__ void cp_async16(uint32_t saddr, const void* gaddr) {
    asm volatile("cp.async.cg.shared.global [%0], [%1], 16;"
                 :: "r"(saddr), "l"(gaddr));
}
#define CP_COMMIT() asm volatile("cp.async.commit_group;" ::: "memory")
#define CP_WAIT0()  asm volatile("cp.async.wait_group 0;" ::: "memory")

__device__ __forceinline__ void mma16816(float* c, const uint32_t* a,
                                         const uint32_t* b) {
    asm volatile(
        "mma.sync.aligned.m16n8k16.row.col.f32.f16.f16.f32 "
        "{%0,%1,%2,%3}, {%4,%5,%6,%7}, {%8,%9}, {%0,%1,%2,%3};"
        : "+f"(c[0]), "+f"(c[1]), "+f"(c[2]), "+f"(c[3])
        : "r"(a[0]), "r"(a[1]), "r"(a[2]), "r"(a[3]), "r"(b[0]), "r"(b[1]));
}
__device__ __forceinline__ void ldsm4(uint32_t* r, uint32_t addr) {
    asm volatile("ldmatrix.sync.aligned.m8n8.x4.shared.b16 {%0,%1,%2,%3}, [%4];"
                 : "=r"(r[0]), "=r"(r[1]), "=r"(r[2]), "=r"(r[3]) : "r"(addr));
}
// fp16 tile (128B rows): 16B-granule XOR swizzle
__device__ __forceinline__ uint32_t swzH(int row, int col) {
    return (uint32_t)(row * 128 + (col ^ ((row & 7) << 4)));
}
// fp32 tile (256B rows): 32B-granule XOR swizzle (gemm1 B tile)
__device__ __forceinline__ uint32_t swzF(int row, int col) {
    return (uint32_t)(row * 256 + (col ^ ((row & 7) << 5)));
}
// fp32 tile (256B rows): 16B-granule XOR swizzle -- conflict-free 8-row reads
__device__ __forceinline__ uint32_t swzF16(int row, int col) {
    return (uint32_t)(row * 256 + (col ^ ((row & 7) << 4)));
}
__device__ __forceinline__ uint32_t h2u(__half2 h) {
    union { __half2 h; uint32_t u; } c; c.h = h; return c.u;
}
__device__ __forceinline__ uint32_t f2h2(float a, float b) {
    return h2u(__floats2half2_rn(a, b));
}

// ============================================================================
// gemm1: WcT[m,n] = sum_k Wo[k,m] * Wv[n,k]   (fp32 in, fp16 out)
// BM=64 (m), BN=64 (n), BK=64.  4 warps, warp 32x32.
// Bias CTAs (blockIdx.y == 16): t[j] = 2048*sum_i bv[i]*Wo[i,j] + bo[j].
// ============================================================================
#define G1T 128
constexpr uint32_t G1_AT  = 64u * 272u;          // 17408
constexpr uint32_t G1_BT  = 64u * 256u;          // 16384
constexpr uint32_t G1_STG = G1_AT + G1_BT;       // 33792
constexpr uint32_t SM_G1  = 2u * G1_STG;         // 67584

__global__ __launch_bounds__(G1T)
void gemm1_w(const float* __restrict__ Wo, const float* __restrict__ Wv,
             __half* __restrict__ WcT,
             const float* __restrict__ bv, const float* __restrict__ bo,
             float* __restrict__ tvec)
{
    const int tid = threadIdx.x;

    if (blockIdx.y == 16) {     // ---- bias CTAs
        __shared__ float red[2][64];
        const int c = tid & 63, q = tid >> 6;
        const int j = blockIdx.x * 64 + c;
        const int i0 = q * 512;
        float s = 0.0f;
        #pragma unroll 16
        for (int i = 0; i < 512; i++)
            s = fmaf(bv[i0 + i], Wo[(size_t)(i0 + i) * 1024 + j], s);
        red[q][c] = s;
        __syncthreads();
        if (q == 0)
            tvec[j] = 2048.0f * (red[0][c] + red[1][c]) + bo[j];
        return;
    }

    extern __shared__ char smem[];
    const uint32_t sb = smem_u32(smem);
    const int wid = tid >> 5, lane = tid & 31;
    const int g = lane >> 2, tig = lane & 3;
    const int mb = blockIdx.y * 64;
    const int nb = blockIdx.x * 64;
    const int wm = (wid & 1) * 32;
    const int wn = (wid >> 1) * 32;

    float acc[2][4][4];
    #pragma unroll
    for (int mt = 0; mt < 2; mt++)
        #pragma unroll
        for (int nt = 0; nt < 4; nt++)
            #pragma unroll
            for (int i = 0; i < 4; i++) acc[mt][nt][i] = 0.0f;

    auto issue = [&](int c) {
        const int k0 = c * 64;
        const uint32_t stg = sb + (uint32_t)(c & 1) * G1_STG;
        #pragma unroll
        for (int i = 0; i < 8; i++) {          // A: Wo rows, 272B pitch
            const int li = i * G1T + tid;
            const int r = li >> 4, gc = li & 15;
            cp_async16(stg + (uint32_t)(r * 272 + gc * 16),
                       Wo + (size_t)(k0 + r) * 1024 + mb + gc * 4);
        }
        #pragma unroll
        for (int i = 0; i < 8; i++) {          // B: Wv rows, swzF
            const int li = i * G1T + tid;
            const int r = li >> 4, gc = li & 15;
            cp_async16(stg + G1_AT + swzF(r, gc * 16),
                       Wv + (size_t)(nb + r) * 1024 + k0 + gc * 4);
        }
        CP_COMMIT();
    };

    issue(0);

    for (int c = 0; c < 16; c++) {
        CP_WAIT0();
        __syncthreads();
        if (c + 1 < 16) issue(c + 1);

        const char* baseA = smem + (size_t)(c & 1) * G1_STG;
        const char* baseB = baseA + G1_AT;

        #pragma unroll
        for (int ks = 0; ks < 4; ks++) {
            const int ka = ks * 16 + tig * 2;
            uint32_t aF[2][4], bF[4][2];

            #pragma unroll
            for (int mt = 0; mt < 2; mt++) {
                const int m0 = wm + mt * 16 + g, m1 = m0 + 8;
                const char* r0p = baseA + ka * 272;
                const char* r1p = r0p + 272;
                const char* r8p = r0p + 8 * 272;
                const char* r9p = r8p + 272;
                aF[mt][0] = f2h2(*(const float*)(r0p + m0 * 4),
                                 *(const float*)(r1p + m0 * 4));
                aF[mt][1] = f2h2(*(const float*)(r0p + m1 * 4),
                                 *(const float*)(r1p + m1 * 4));
                aF[mt][2] = f2h2(*(const float*)(r8p + m0 * 4),
                                 *(const float*)(r9p + m0 * 4));
                aF[mt][3] = f2h2(*(const float*)(r8p + m1 * 4),
                                 *(const float*)(r9p + m1 * 4));
            }
            #pragma unroll
            for (int nt = 0; nt < 4; nt++) {
                const int row = wn + nt * 8 + g;
                const int cb = ka * 4;
                float2 lo = *(const float2*)(baseB + swzF(row, cb));
                float2 hi = *(const float2*)(baseB + swzF(row, cb + 32));
                bF[nt][0] = f2h2(lo.x, lo.y);
                bF[nt][1] = f2h2(hi.x, hi.y);
            }
            #pragma unroll
            for (int mt = 0; mt < 2; mt++)
                #pragma unroll
                for (int nt = 0; nt < 4; nt++)
                    mma16816(acc[mt][nt], aF[mt], bF[nt]);
        }
        __syncthreads();
    }

    #pragma unroll
    for (int mt = 0; mt < 2; mt++) {
        const size_t r0 = (size_t)mb + wm + mt * 16 + g;
        #pragma unroll
        for (int nt = 0; nt < 4; nt++) {
            const int c0 = nb + wn + nt * 8 + tig * 2;
            *(__half2*)(WcT + r0 * 1024 + c0) =
                __floats2half2_rn(acc[mt][nt][0], acc[mt][nt][1]);
            *(__half2*)(WcT + (r0 + 8) * 1024 + c0) =
                __floats2half2_rn(acc[mt][nt][2], acc[mt][nt][3]);
        }
    }
}

// ============================================================================
// gemm2: out[m,n] = 2048 * sum_k x[m,k] * WcT[n,k] + t[n]
// BM=64, BN=128, 256 threads = 8 warps, warp tile 32x32 (2 over M, 4 over N).
// ~100 regs/thread -> 2 CTAs/SM natural -> 4 warps/SMSP, no spills.
// A = x fp32, swzF16 (conflict-free); B = WcT fp16 (swzH + ldmatrix).
// ============================================================================
#define G2T 256
constexpr uint32_t G2_AT  = 64u * 256u;          // 16384
constexpr uint32_t G2_BT  = 128u * 128u;         // 16384
constexpr uint32_t G2_STG = G2_AT + G2_BT;       // 32768
constexpr uint32_t SM_G2  = 2u * G2_STG;         // 65536

__global__ __launch_bounds__(G2T)
void gemm2_x(const float* __restrict__ x, const __half* __restrict__ B,
             float* __restrict__ C, const float* __restrict__ bias)
{
    extern __shared__ char smem[];
    const uint32_t sb = smem_u32(smem);
    const int tid = threadIdx.x;
    const int wid = tid >> 5, lane = tid & 31;
    const int g = lane >> 2, tig = lane & 3;
    const int bm = blockIdx.y, bn = blockIdx.x;
    const int wm = (wid & 1) * 32;             // 2 warps over M
    const int wn = (wid >> 1) * 32;            // 4 warps over N
    const int lm = lane >> 3, lr = lane & 7;
    const int N = 1024, K = 1024;

    const float* Ab = x + (size_t)bm * 64 * K;
    const __half* Bb = B + (size_t)bn * 128 * K;

    float acc[2][4][4];
    #pragma unroll
    for (int mt = 0; mt < 2; mt++)
        #pragma unroll
        for (int nt = 0; nt < 4; nt++)
            #pragma unroll
            for (int i = 0; i < 4; i++) acc[mt][nt][i] = 0.0f;

    auto issue = [&](int c) {
        const int k0 = c * 64;
        const uint32_t stg = sb + (uint32_t)(c & 1) * G2_STG;
        #pragma unroll
        for (int i = 0; i < 4; i++) {          // A: 64 rows x 16 granules
            const int li = i * G2T + tid;
            const int r = li >> 4, gc = li & 15;
            cp_async16(stg + swzF16(r, gc * 16),
                       Ab + (size_t)r * K + k0 + gc * 4);
        }
        #pragma unroll
        for (int i = 0; i < 4; i++) {          // B: 128 rows x 8 granules
            const int li = i * G2T + tid;
            const int r = li >> 3, gc = li & 7;
            cp_async16(stg + G2_AT + swzH(r, gc * 16),
                       Bb + (size_t)r * K + k0 + gc * 8);
        }
        CP_COMMIT();
    };

    issue(0);

    for (int c = 0; c < 16; c++) {
        CP_WAIT0();
        __syncthreads();
        if (c + 1 < 16) issue(c + 1);

        const char* baseA = smem + (size_t)(c & 1) * G2_STG;
        const uint32_t tB = sb + (uint32_t)(c & 1) * G2_STG + G2_AT;

        #pragma unroll
        for (int ks = 0; ks < 4; ks++) {
            const int kb = ks * 32;                 // fp16-tile byte col
            uint32_t aF[2][4], bF[2][4];

            const int cb = ks * 64 + tig * 8;       // fp32-tile byte col
            #pragma unroll
            for (int mt = 0; mt < 2; mt++) {
                const int r0 = wm + mt * 16 + g, r1 = r0 + 8;
                float2 v00 = *(const float2*)(baseA + swzF16(r0, cb));
                float2 v10 = *(const float2*)(baseA + swzF16(r1, cb));
                float2 v01 = *(const float2*)(baseA + swzF16(r0, cb + 32));
                float2 v11 = *(const float2*)(baseA + swzF16(r1, cb + 32));
                aF[mt][0] = f2h2(v00.x, v00.y);
                aF[mt][1] = f2h2(v10.x, v10.y);
                aF[mt][2] = f2h2(v01.x, v01.y);
                aF[mt][3] = f2h2(v11.x, v11.y);
            }
            #pragma unroll
            for (int nt2 = 0; nt2 < 2; nt2++) {
                const int row = wn + (2 * nt2 + (lm >> 1)) * 8 + lr;
                ldsm4(bF[nt2], tB + swzH(row, kb + (lm & 1) * 16));
            }
            #pragma unroll
            for (int mt = 0; mt < 2; mt++)
                #pragma unroll
                for (int nt2 = 0; nt2 < 2; nt2++) {
                    mma16816(acc[mt][2 * nt2],     aF[mt], &bF[nt2][0]);
                    mma16816(acc[mt][2 * nt2 + 1], aF[mt], &bF[nt2][2]);
                }
        }
        __syncthreads();
    }

    // ---- epilogue
    #pragma unroll
    for (int mt = 0; mt < 2; mt++) {
        const size_t r0 = (size_t)bm * 64 + wm + mt * 16 + g;
        #pragma unroll
        for (int nt = 0; nt < 4; nt++) {
            const int c0 = bn * 128 + wn + nt * 8 + tig * 2;
            const float bx = bias[c0], by = bias[c0 + 1];
            *(float2*)(C + r0 * N + c0) =
                make_float2(2048.0f * acc[mt][nt][0] + bx,
                            2048.0f * acc[mt][nt][1] + by);
            *(float2*)(C + (r0 + 8) * N + c0) =
                make_float2(2048.0f * acc[mt][nt][2] + bx,
                            2048.0f * acc[mt][nt][3] + by);
        }
    }
}

// ---------------------------------------------------------------------------
extern "C" void kernel_launch(void* const* d_in, const int* in_sizes, int n_in,
                              void* d_out, int out_size)
{
    const float* x  = (const float*)d_in[0];
    // d_in[1..5] = encoder_x, Wq, bq, Wk, bk -- mathematically dead
    const float* Wv = (const float*)d_in[6];
    const float* bv = (const float*)d_in[7];
    const float* Wo = (const float*)d_in[8];
    const float* bo = (const float*)d_in[9];
    float* out = (float*)d_out;

    __half* WcTh;
    float* t;
    cudaGetSymbolAddress((void**)&WcTh, g_WcTh);
    cudaGetSymbolAddress((void**)&t,    g_t);

    static int smem_set = 0;
    if (!smem_set) {
        cudaFuncSetAttribute(gemm1_w,
                             cudaFuncAttributeMaxDynamicSharedMemorySize, SM_G1);
        cudaFuncSetAttribute(gemm2_x,
                             cudaFuncAttributeMaxDynamicSharedMemorySize, SM_G2);
        smem_set = 1;
    }

    // 1) gemm1: WcT = Wo^T @ Wv^T  (256 CTAs) + 16 bias CTAs -> 272 CTAs
    {
        dim3 g(16, 17);   // y==16 -> bias CTAs
        gemm1_w<<<g, G1T, SM_G1>>>(Wo, Wv, WcTh, bv, bo, t);
    }

    // 2) gemm2: out = 2048 * x @ Wc + t  (1024 CTAs, 2/SM)
    {
        dim3 g(8, 128);
        gemm2_x<<<g, G2T, SM_G2>>>(x, WcTh, out, t);
    }
}

// round 11
// speedup vs baseline: 1.4243x; 1.4243x over previous
#include <cuda_runtime.h>
#include <cuda_fp16.h>
#include <stdint.h>

// ============================================================================
// CrossAttention collapses algebraically:
//   softmax over k sums to 1 per query -> sum over (q,k) of scores = L = 2048.
//   einsum 'bvhd,bhqk->bvhd' has no shared contraction index, so attn = v*2048:
//     out = 2048 * x @ (Wv@Wo) + (2048 * bv@Wo + bo)
// encoder_x / Wq / bq / Wk / bk are dead inputs.
//
// R11: gemm2 back to the 64x64-warp-tile shape (lowest smem bytes/MMA: ~250,
// matching the ~28us tensor-pipe floor) with a software pipeline over ks:
// ping-pong fragment registers, frags for ks+1 loaded under ks's MMAs, and
// cross-chunk ks0 prefetch after the cp.async wait. gemm1+bias from R9.
// ============================================================================

// ---------------- scratch ----------------------------------------------------
__device__ __half g_WcTh[1024u * 1024u];
__device__ float  g_t[1024];

// ---------------- helpers ----------------------------------------------------
__device__ __forceinline__ uint32_t smem_u32(const void* p) {
    uint32_t a;
    asm("{ .reg .u64 t; cvta.to.shared.u64 t, %1; cvt.u32.u64 %0, t; }"
        : "=r"(a) : "l"(p));
    return a;
}
__device__ __forceinline__ void cp_async16(uint32_t saddr, const void* gaddr) {
    asm volatile("cp.async.cg.shared.global [%0], [%1], 16;"
                 :: "r"(saddr), "l"(gaddr));
}
#define CP_COMMIT() asm volatile("cp.async.commit_group;" ::: "memory")
#define CP_WAIT0()  asm volatile("cp.async.wait_group 0;" ::: "memory")

__device__ __forceinline__ void mma16816(float* c, const uint32_t* a,
                                         const uint32_t* b) {
    asm volatile(
        "mma.sync.aligned.m16n8k16.row.col.f32.f16.f16.f32 "
        "{%0,%1,%2,%3}, {%4,%5,%6,%7}, {%8,%9}, {%0,%1,%2,%3};"
        : "+f"(c[0]), "+f"(c[1]), "+f"(c[2]), "+f"(c[3])
        : "r"(a[0]), "r"(a[1]), "r"(a[2]), "r"(a[3]), "r"(b[0]), "r"(b[1]));
}
__device__ __forceinline__ void ldsm4(uint32_t* r, uint32_t addr) {
    asm volatile("ldmatrix.sync.aligned.m8n8.x4.shared.b16 {%0,%1,%2,%3}, [%4];"
                 : "=r"(r[0]), "=r"(r[1]), "=r"(r[2]), "=r"(r[3]) : "r"(addr));
}
// fp16 tile (128B rows): 16B-granule XOR swizzle
__device__ __forceinline__ uint32_t swzH(int row, int col) {
    return (uint32_t)(row * 128 + (col ^ ((row & 7) << 4)));
}
// fp32 tile (256B rows): 32B-granule XOR swizzle
__device__ __forceinline__ uint32_t swzF(int row, int col) {
    return (uint32_t)(row * 256 + (col ^ ((row & 7) << 5)));
}
__device__ __forceinline__ uint32_t h2u(__half2 h) {
    union { __half2 h; uint32_t u; } c; c.h = h; return c.u;
}
__device__ __forceinline__ uint32_t f2h2(float a, float b) {
    return h2u(__floats2half2_rn(a, b));
}

// ============================================================================
// gemm1: WcT[m,n] = sum_k Wo[k,m] * Wv[n,k]   (fp32 in, fp16 out)
// BM=64 (m), BN=64 (n), BK=64.  4 warps, warp 32x32.  (R9, measured good.)
// Bias CTAs (blockIdx.y == 16): t[j] = 2048*sum_i bv[i]*Wo[i,j] + bo[j].
// ============================================================================
#define G1T 128
constexpr uint32_t G1_AT  = 64u * 272u;
constexpr uint32_t G1_BT  = 64u * 256u;
constexpr uint32_t G1_STG = G1_AT + G1_BT;
constexpr uint32_t SM_G1  = 2u * G1_STG;

__global__ __launch_bounds__(G1T)
void gemm1_w(const float* __restrict__ Wo, const float* __restrict__ Wv,
             __half* __restrict__ WcT,
             const float* __restrict__ bv, const float* __restrict__ bo,
             float* __restrict__ tvec)
{
    const int tid = threadIdx.x;

    if (blockIdx.y == 16) {     // ---- bias CTAs
        __shared__ float red[2][64];
        const int c = tid & 63, q = tid >> 6;
        const int j = blockIdx.x * 64 + c;
        const int i0 = q * 512;
        float s = 0.0f;
        #pragma unroll 16
        for (int i = 0; i < 512; i++)
            s = fmaf(bv[i0 + i], Wo[(size_t)(i0 + i) * 1024 + j], s);
        red[q][c] = s;
        __syncthreads();
        if (q == 0)
            tvec[j] = 2048.0f * (red[0][c] + red[1][c]) + bo[j];
        return;
    }

    extern __shared__ char smem[];
    const uint32_t sb = smem_u32(smem);
    const int wid = tid >> 5, lane = tid & 31;
    const int g = lane >> 2, tig = lane & 3;
    const int mb = blockIdx.y * 64;
    const int nb = blockIdx.x * 64;
    const int wm = (wid & 1) * 32;
    const int wn = (wid >> 1) * 32;

    float acc[2][4][4];
    #pragma unroll
    for (int mt = 0; mt < 2; mt++)
        #pragma unroll
        for (int nt = 0; nt < 4; nt++)
            #pragma unroll
            for (int i = 0; i < 4; i++) acc[mt][nt][i] = 0.0f;

    auto issue = [&](int c) {
        const int k0 = c * 64;
        const uint32_t stg = sb + (uint32_t)(c & 1) * G1_STG;
        #pragma unroll
        for (int i = 0; i < 8; i++) {
            const int li = i * G1T + tid;
            const int r = li >> 4, gc = li & 15;
            cp_async16(stg + (uint32_t)(r * 272 + gc * 16),
                       Wo + (size_t)(k0 + r) * 1024 + mb + gc * 4);
        }
        #pragma unroll
        for (int i = 0; i < 8; i++) {
            const int li = i * G1T + tid;
            const int r = li >> 4, gc = li & 15;
            cp_async16(stg + G1_AT + swzF(r, gc * 16),
                       Wv + (size_t)(nb + r) * 1024 + k0 + gc * 4);
        }
        CP_COMMIT();
    };

    issue(0);

    for (int c = 0; c < 16; c++) {
        CP_WAIT0();
        __syncthreads();
        if (c + 1 < 16) issue(c + 1);

        const char* baseA = smem + (size_t)(c & 1) * G1_STG;
        const char* baseB = baseA + G1_AT;

        #pragma unroll
        for (int ks = 0; ks < 4; ks++) {
            const int ka = ks * 16 + tig * 2;
            uint32_t aF[2][4], bF[4][2];

            #pragma unroll
            for (int mt = 0; mt < 2; mt++) {
                const int m0 = wm + mt * 16 + g, m1 = m0 + 8;
                const char* r0p = baseA + ka * 272;
                const char* r1p = r0p + 272;
                const char* r8p = r0p + 8 * 272;
                const char* r9p = r8p + 272;
                aF[mt][0] = f2h2(*(const float*)(r0p + m0 * 4),
                                 *(const float*)(r1p + m0 * 4));
                aF[mt][1] = f2h2(*(const float*)(r0p + m1 * 4),
                                 *(const float*)(r1p + m1 * 4));
                aF[mt][2] = f2h2(*(const float*)(r8p + m0 * 4),
                                 *(const float*)(r9p + m0 * 4));
                aF[mt][3] = f2h2(*(const float*)(r8p + m1 * 4),
                                 *(const float*)(r9p + m1 * 4));
            }
            #pragma unroll
            for (int nt = 0; nt < 4; nt++) {
                const int row = wn + nt * 8 + g;
                const int cb = ka * 4;
                float2 lo = *(const float2*)(baseB + swzF(row, cb));
                float2 hi = *(const float2*)(baseB + swzF(row, cb + 32));
                bF[nt][0] = f2h2(lo.x, lo.y);
                bF[nt][1] = f2h2(hi.x, hi.y);
            }
            #pragma unroll
            for (int mt = 0; mt < 2; mt++)
                #pragma unroll
                for (int nt = 0; nt < 4; nt++)
                    mma16816(acc[mt][nt], aF[mt], bF[nt]);
        }
        __syncthreads();
    }

    #pragma unroll
    for (int mt = 0; mt < 2; mt++) {
        const size_t r0 = (size_t)mb + wm + mt * 16 + g;
        #pragma unroll
        for (int nt = 0; nt < 4; nt++) {
            const int c0 = nb + wn + nt * 8 + tig * 2;
            *(__half2*)(WcT + r0 * 1024 + c0) =
                __floats2half2_rn(acc[mt][nt][0], acc[mt][nt][1]);
            *(__half2*)(WcT + (r0 + 8) * 1024 + c0) =
                __floats2half2_rn(acc[mt][nt][2], acc[mt][nt][3]);
        }
    }
}

// ============================================================================
// gemm2: out[m,n] = 2048 * sum_k x[m,k] * WcT[n,k] + t[n]
// BM=128, BN=256, 8 warps (2 over M x 4 over N), warp tile 64x64.
// A = x fp32 (swzF, in-kernel cvt); B = WcT fp16 (swzH + ldmatrix).
// ks-pipelined fragments (ping-pong register sets) + cross-chunk prefetch.
// ============================================================================
#define G2T 256
constexpr uint32_t G2_AT  = 128u * 256u;         // 32768 (fp32 A)
constexpr uint32_t G2_BT  = 256u * 128u;         // 32768 (fp16 B)
constexpr uint32_t G2_STG = G2_AT + G2_BT;       // 65536
constexpr uint32_t SM_G2  = 2u * G2_STG;         // 131072

__global__ __launch_bounds__(G2T)
void gemm2_x(const float* __restrict__ x, const __half* __restrict__ B,
             float* __restrict__ C, const float* __restrict__ bias)
{
    extern __shared__ char smem[];
    const uint32_t sb = smem_u32(smem);
    const int tid = threadIdx.x;
    const int wid = tid >> 5, lane = tid & 31;
    const int g = lane >> 2, tig = lane & 3;
    const int bm = blockIdx.y, bn = blockIdx.x;
    const int wm = (wid & 1) * 64;             // 2 warps over M
    const int wn = (wid >> 1) * 64;            // 4 warps over N
    const int lm = lane >> 3, lr = lane & 7;
    const int N = 1024, K = 1024;

    const float* Ab = x + (size_t)bm * 128 * K;
    const __half* Bb = B + (size_t)bn * 256 * K;

    float acc[4][8][4];
    #pragma unroll
    for (int mt = 0; mt < 4; mt++)
        #pragma unroll
        for (int nt = 0; nt < 8; nt++)
            #pragma unroll
            for (int i = 0; i < 4; i++) acc[mt][nt][i] = 0.0f;

    auto issue = [&](int c) {
        const int k0 = c * 64;
        const uint32_t stg = sb + (uint32_t)(c & 1) * G2_STG;
        #pragma unroll
        for (int i = 0; i < 8; i++) {          // A: 128 rows x 16 granules
            const int li = i * G2T + tid;
            const int r = li >> 4, gc = li & 15;
            cp_async16(stg + swzF(r, gc * 16),
                       Ab + (size_t)r * K + k0 + gc * 4);
        }
        #pragma unroll
        for (int i = 0; i < 8; i++) {          // B: 256 rows x 8 granules
            const int li = i * G2T + tid;
            const int r = li >> 3, gc = li & 7;
            cp_async16(stg + G2_AT + swzH(r, gc * 16),
                       Bb + (size_t)r * K + k0 + gc * 8);
        }
        CP_COMMIT();
    };

    // fragment loaders (buffer selected by chunk parity)
    auto loadA = [&](int cb01, int ks, uint32_t aF[4][4]) {
        const char* baseA = smem + (size_t)cb01 * G2_STG;
        const int cb = ks * 64 + tig * 8;
        #pragma unroll
        for (int mt = 0; mt < 4; mt++) {
            const int r0 = wm + mt * 16 + g, r1 = r0 + 8;
            float2 v00 = *(const float2*)(baseA + swzF(r0, cb));
            float2 v10 = *(const float2*)(baseA + swzF(r1, cb));
            float2 v01 = *(const float2*)(baseA + swzF(r0, cb + 32));
            float2 v11 = *(const float2*)(baseA + swzF(r1, cb + 32));
            aF[mt][0] = f2h2(v00.x, v00.y);
            aF[mt][1] = f2h2(v10.x, v10.y);
            aF[mt][2] = f2h2(v01.x, v01.y);
            aF[mt][3] = f2h2(v11.x, v11.y);
        }
    };
    auto loadB = [&](int cb01, int ks, uint32_t bF[4][4]) {
        const uint32_t tB = sb + (uint32_t)cb01 * G2_STG + G2_AT;
        const int kb = ks * 32;
        #pragma unroll
        for (int nt2 = 0; nt2 < 4; nt2++) {
            const int row = wn + (2 * nt2 + (lm >> 1)) * 8 + lr;
            ldsm4(bF[nt2], tB + swzH(row, kb + (lm & 1) * 16));
        }
    };
    auto domma = [&](uint32_t aF[4][4], uint32_t bF[4][4]) {
        #pragma unroll
        for (int mt = 0; mt < 4; mt++)
            #pragma unroll
            for (int nt2 = 0; nt2 < 4; nt2++) {
                mma16816(acc[mt][2 * nt2],     aF[mt], &bF[nt2][0]);
                mma16816(acc[mt][2 * nt2 + 1], aF[mt], &bF[nt2][2]);
            }
    };

    uint32_t aP[2][4][4], bP[2][4][4];   // ping-pong fragment sets

    issue(0);
    CP_WAIT0();
    __syncthreads();
    issue(1);
    loadA(0, 0, aP[0]);
    loadB(0, 0, bP[0]);

    for (int c = 0; c < 16; c++) {
        const int b01 = c & 1;
        // ks = 0..2: prefetch ks+1 under ks's MMAs
        #pragma unroll
        for (int ks = 0; ks < 3; ks++) {
            loadA(b01, ks + 1, aP[(ks + 1) & 1]);
            loadB(b01, ks + 1, bP[(ks + 1) & 1]);
            domma(aP[ks & 1], bP[ks & 1]);
        }
        // chunk boundary: c+1's data guaranteed after wait; prefetch its ks0
        if (c < 15) {
            CP_WAIT0();
            __syncthreads();
            loadA(b01 ^ 1, 0, aP[0]);
            loadB(b01 ^ 1, 0, bP[0]);
            if (c < 14) issue(c + 2);
        }
        // ks = 3 (frags in set 1)
        domma(aP[1], bP[1]);
    }

    // ---- epilogue
    #pragma unroll
    for (int mt = 0; mt < 4; mt++) {
        const size_t r0 = (size_t)bm * 128 + wm + mt * 16 + g;
        #pragma unroll
        for (int nt = 0; nt < 8; nt++) {
            const int c0 = bn * 256 + wn + nt * 8 + tig * 2;
            const float bx = bias[c0], by = bias[c0 + 1];
            *(float2*)(C + r0 * N + c0) =
                make_float2(2048.0f * acc[mt][nt][0] + bx,
                            2048.0f * acc[mt][nt][1] + by);
            *(float2*)(C + (r0 + 8) * N + c0) =
                make_float2(2048.0f * acc[mt][nt][2] + bx,
                            2048.0f * acc[mt][nt][3] + by);
        }
    }
}

// ---------------------------------------------------------------------------
extern "C" void kernel_launch(void* const* d_in, const int* in_sizes, int n_in,
                              void* d_out, int out_size)
{
    const float* x  = (const float*)d_in[0];
    // d_in[1..5] = encoder_x, Wq, bq, Wk, bk -- mathematically dead
    const float* Wv = (const float*)d_in[6];
    const float* bv = (const float*)d_in[7];
    const float* Wo = (const float*)d_in[8];
    const float* bo = (const float*)d_in[9];
    float* out = (float*)d_out;

    __half* WcTh;
    float* t;
    cudaGetSymbolAddress((void**)&WcTh, g_WcTh);
    cudaGetSymbolAddress((void**)&t,    g_t);

    static int smem_set = 0;
    if (!smem_set) {
        cudaFuncSetAttribute(gemm1_w,
                             cudaFuncAttributeMaxDynamicSharedMemorySize, SM_G1);
        cudaFuncSetAttribute(gemm2_x,
                             cudaFuncAttributeMaxDynamicSharedMemorySize, SM_G2);
        smem_set = 1;
    }

    // 1) gemm1: WcT = Wo^T @ Wv^T  (256 CTAs) + 16 bias CTAs -> 272 CTAs
    {
        dim3 g(16, 17);   // y==16 -> bias CTAs
        gemm1_w<<<g, G1T, SM_G1>>>(Wo, Wv, WcTh, bv, bo, t);
    }

    // 2) gemm2: out = 2048 * x @ Wc + t  (256 CTAs, 8 warps, 64x64 warp tile)
    {
        dim3 g(4, 64);
        gemm2_x<<<g, G2T, SM_G2>>>(x, WcTh, out, t);
    }
}

// round 12
// speedup vs baseline: 1.6040x; 1.1262x over previous
#include <cuda_runtime.h>
#include <cuda_fp16.h>
#include <stdint.h>

// ============================================================================
// CrossAttention collapses algebraically:
//   softmax over k sums to 1 per query -> sum over (q,k) of scores = L = 2048.
//   einsum 'bvhd,bhqk->bvhd' has no shared contraction index, so attn = v*2048:
//     out = 2048 * x @ (Wv@Wo) + (2048 * bv@Wo + bo)
// encoder_x / Wq / bq / Wk / bk are dead inputs.
//
// R12: recombination of measured-best pieces.
//  - gemm2: R8 config verbatim (64x128 CTA, 4 warps, 32x64 warp tile, 1024
//    CTAs, 3 CTAs/SM) -- best measured at 54.7us. launch_bounds(128,3) pins
//    residency; B (ldmatrix) frags issued before A (LDS.64+cvt) chain.
//  - gemm1: 64x64 tiles, 272 CTAs, fused bias CTAs (measured 17.2us segment).
// ============================================================================

// ---------------- scratch ----------------------------------------------------
__device__ __half g_WcTh[1024u * 1024u];
__device__ float  g_t[1024];

// ---------------- helpers ----------------------------------------------------
__device__ __forceinline__ uint32_t smem_u32(const void* p) {
    uint32_t a;
    asm("{ .reg .u64 t; cvta.to.shared.u64 t, %1; cvt.u32.u64 %0, t; }"
        : "=r"(a) : "l"(p));
    return a;
}
__device__ __forceinline__ void cp_async16(uint32_t saddr, const void* gaddr) {
    asm volatile("cp.async.cg.shared.global [%0], [%1], 16;"
                 :: "r"(saddr), "l"(gaddr));
}
#define CP_COMMIT() asm volatile("cp.async.commit_group;" ::: "memory")
#define CP_WAIT0()  asm volatile("cp.async.wait_group 0;" ::: "memory")

__device__ __forceinline__ void mma16816(float* c, const uint32_t* a,
                                         const uint32_t* b) {
    asm volatile(
        "mma.sync.aligned.m16n8k16.row.col.f32.f16.f16.f32 "
        "{%0,%1,%2,%3}, {%4,%5,%6,%7}, {%8,%9}, {%0,%1,%2,%3};"
        : "+f"(c[0]), "+f"(c[1]), "+f"(c[2]), "+f"(c[3])
        : "r"(a[0]), "r"(a[1]), "r"(a[2]), "r"(a[3]), "r"(b[0]), "r"(b[1]));
}
__device__ __forceinline__ void ldsm4(uint32_t* r, uint32_t addr) {
    asm volatile("ldmatrix.sync.aligned.m8n8.x4.shared.b16 {%0,%1,%2,%3}, [%4];"
                 : "=r"(r[0]), "=r"(r[1]), "=r"(r[2]), "=r"(r[3]) : "r"(addr));
}
// fp16 tile (128B rows): 16B-granule XOR swizzle
__device__ __forceinline__ uint32_t swzH(int row, int col) {
    return (uint32_t)(row * 128 + (col ^ ((row & 7) << 4)));
}
// fp32 tile (256B rows): 32B-granule XOR swizzle
__device__ __forceinline__ uint32_t swzF(int row, int col) {
    return (uint32_t)(row * 256 + (col ^ ((row & 7) << 5)));
}
__device__ __forceinline__ uint32_t h2u(__half2 h) {
    union { __half2 h; uint32_t u; } c; c.h = h; return c.u;
}
__device__ __forceinline__ uint32_t f2h2(float a, float b) {
    return h2u(__floats2half2_rn(a, b));
}

// ============================================================================
// gemm1: WcT[m,n] = sum_k Wo[k,m] * Wv[n,k]   (fp32 in, fp16 out)
// BM=64 (m), BN=64 (n), BK=64.  4 warps, warp 32x32.
// Bias CTAs (blockIdx.y == 16): t[j] = 2048*sum_i bv[i]*Wo[i,j] + bo[j].
// ============================================================================
#define G1T 128
constexpr uint32_t G1_AT  = 64u * 272u;
constexpr uint32_t G1_BT  = 64u * 256u;
constexpr uint32_t G1_STG = G1_AT + G1_BT;
constexpr uint32_t SM_G1  = 2u * G1_STG;

__global__ __launch_bounds__(G1T)
void gemm1_w(const float* __restrict__ Wo, const float* __restrict__ Wv,
             __half* __restrict__ WcT,
             const float* __restrict__ bv, const float* __restrict__ bo,
             float* __restrict__ tvec)
{
    const int tid = threadIdx.x;

    if (blockIdx.y == 16) {     // ---- bias CTAs
        __shared__ float red[2][64];
        const int c = tid & 63, q = tid >> 6;
        const int j = blockIdx.x * 64 + c;
        const int i0 = q * 512;
        float s = 0.0f;
        #pragma unroll 16
        for (int i = 0; i < 512; i++)
            s = fmaf(bv[i0 + i], Wo[(size_t)(i0 + i) * 1024 + j], s);
        red[q][c] = s;
        __syncthreads();
        if (q == 0)
            tvec[j] = 2048.0f * (red[0][c] + red[1][c]) + bo[j];
        return;
    }

    extern __shared__ char smem[];
    const uint32_t sb = smem_u32(smem);
    const int wid = tid >> 5, lane = tid & 31;
    const int g = lane >> 2, tig = lane & 3;
    const int mb = blockIdx.y * 64;
    const int nb = blockIdx.x * 64;
    const int wm = (wid & 1) * 32;
    const int wn = (wid >> 1) * 32;

    float acc[2][4][4];
    #pragma unroll
    for (int mt = 0; mt < 2; mt++)
        #pragma unroll
        for (int nt = 0; nt < 4; nt++)
            #pragma unroll
            for (int i = 0; i < 4; i++) acc[mt][nt][i] = 0.0f;

    auto issue = [&](int c) {
        const int k0 = c * 64;
        const uint32_t stg = sb + (uint32_t)(c & 1) * G1_STG;
        #pragma unroll
        for (int i = 0; i < 8; i++) {          // A: Wo rows, 272B pitch
            const int li = i * G1T + tid;
            const int r = li >> 4, gc = li & 15;
            cp_async16(stg + (uint32_t)(r * 272 + gc * 16),
                       Wo + (size_t)(k0 + r) * 1024 + mb + gc * 4);
        }
        #pragma unroll
        for (int i = 0; i < 8; i++) {          // B: Wv rows, swzF
            const int li = i * G1T + tid;
            const int r = li >> 4, gc = li & 15;
            cp_async16(stg + G1_AT + swzF(r, gc * 16),
                       Wv + (size_t)(nb + r) * 1024 + k0 + gc * 4);
        }
        CP_COMMIT();
    };

    issue(0);

    for (int c = 0; c < 16; c++) {
        CP_WAIT0();
        __syncthreads();
        if (c + 1 < 16) issue(c + 1);

        const char* baseA = smem + (size_t)(c & 1) * G1_STG;
        const char* baseB = baseA + G1_AT;

        #pragma unroll
        for (int ks = 0; ks < 4; ks++) {
            const int ka = ks * 16 + tig * 2;
            uint32_t aF[2][4], bF[4][2];

            #pragma unroll
            for (int mt = 0; mt < 2; mt++) {
                const int m0 = wm + mt * 16 + g, m1 = m0 + 8;
                const char* r0p = baseA + ka * 272;
                const char* r1p = r0p + 272;
                const char* r8p = r0p + 8 * 272;
                const char* r9p = r8p + 272;
                aF[mt][0] = f2h2(*(const float*)(r0p + m0 * 4),
                                 *(const float*)(r1p + m0 * 4));
                aF[mt][1] = f2h2(*(const float*)(r0p + m1 * 4),
                                 *(const float*)(r1p + m1 * 4));
                aF[mt][2] = f2h2(*(const float*)(r8p + m0 * 4),
                                 *(const float*)(r9p + m0 * 4));
                aF[mt][3] = f2h2(*(const float*)(r8p + m1 * 4),
                                 *(const float*)(r9p + m1 * 4));
            }
            #pragma unroll
            for (int nt = 0; nt < 4; nt++) {
                const int row = wn + nt * 8 + g;
                const int cb = ka * 4;
                float2 lo = *(const float2*)(baseB + swzF(row, cb));
                float2 hi = *(const float2*)(baseB + swzF(row, cb + 32));
                bF[nt][0] = f2h2(lo.x, lo.y);
                bF[nt][1] = f2h2(hi.x, hi.y);
            }
            #pragma unroll
            for (int mt = 0; mt < 2; mt++)
                #pragma unroll
                for (int nt = 0; nt < 4; nt++)
                    mma16816(acc[mt][nt], aF[mt], bF[nt]);
        }
        __syncthreads();
    }

    #pragma unroll
    for (int mt = 0; mt < 2; mt++) {
        const size_t r0 = (size_t)mb + wm + mt * 16 + g;
        #pragma unroll
        for (int nt = 0; nt < 4; nt++) {
            const int c0 = nb + wn + nt * 8 + tig * 2;
            *(__half2*)(WcT + r0 * 1024 + c0) =
                __floats2half2_rn(acc[mt][nt][0], acc[mt][nt][1]);
            *(__half2*)(WcT + (r0 + 8) * 1024 + c0) =
                __floats2half2_rn(acc[mt][nt][2], acc[mt][nt][3]);
        }
    }
}

// ============================================================================
// gemm2: out[m,n] = 2048 * sum_k x[m,k] * WcT[n,k] + t[n]
// R8 config: BM=64, BN=128, 4 warps (2 over M x 2 over N), warp tile 32x64.
// A = x fp32 (256B swzF rows, in-kernel cvt); B = WcT fp16 (swzH + ldmatrix).
// 1024 CTAs, 3 CTAs/SM (launch_bounds(128,3) pins residency).
// ============================================================================
#define G2T 128
constexpr uint32_t G2_AT  = 64u * 256u;          // 16384
constexpr uint32_t G2_BT  = 128u * 128u;         // 16384
constexpr uint32_t G2_STG = G2_AT + G2_BT;       // 32768
constexpr uint32_t SM_G2  = 2u * G2_STG;         // 65536

__global__ __launch_bounds__(G2T, 3)
void gemm2_x(const float* __restrict__ x, const __half* __restrict__ B,
             float* __restrict__ C, const float* __restrict__ bias)
{
    extern __shared__ char smem[];
    const uint32_t sb = smem_u32(smem);
    const int tid = threadIdx.x;
    const int wid = tid >> 5, lane = tid & 31;
    const int g = lane >> 2, tig = lane & 3;
    const int bm = blockIdx.y, bn = blockIdx.x;
    const int wm = (wid & 1) * 32;
    const int wn = (wid >> 1) * 64;
    const int lm = lane >> 3, lr = lane & 7;
    const int N = 1024, K = 1024;

    const float* Ab = x + (size_t)bm * 64 * K;
    const __half* Bb = B + (size_t)bn * 128 * K;

    float acc[2][8][4];
    #pragma unroll
    for (int mt = 0; mt < 2; mt++)
        #pragma unroll
        for (int nt = 0; nt < 8; nt++)
            #pragma unroll
            for (int i = 0; i < 4; i++) acc[mt][nt][i] = 0.0f;

    auto issue = [&](int c) {
        const int k0 = c * 64;
        const uint32_t stg = sb + (uint32_t)(c & 1) * G2_STG;
        #pragma unroll
        for (int i = 0; i < 8; i++) {          // A: 64 rows x 16 granules
            const int li = i * G2T + tid;
            const int r = li >> 4, gc = li & 15;
            cp_async16(stg + swzF(r, gc * 16),
                       Ab + (size_t)r * K + k0 + gc * 4);
        }
        #pragma unroll
        for (int i = 0; i < 8; i++) {          // B: 128 rows x 8 granules
            const int li = i * G2T + tid;
            const int r = li >> 3, gc = li & 7;
            cp_async16(stg + G2_AT + swzH(r, gc * 16),
                       Bb + (size_t)r * K + k0 + gc * 8);
        }
        CP_COMMIT();
    };

    issue(0);

    for (int c = 0; c < 16; c++) {
        CP_WAIT0();
        __syncthreads();
        if (c + 1 < 16) issue(c + 1);

        const char* baseA = smem + (size_t)(c & 1) * G2_STG;
        const uint32_t tB = sb + (uint32_t)(c & 1) * G2_STG + G2_AT;

        #pragma unroll
        for (int ks = 0; ks < 4; ks++) {
            const int kb = ks * 32;                 // fp16-tile byte col
            uint32_t aF[2][4], bF[4][4];

            // B first: short ldmatrix chain gets latency cover from A's chain
            #pragma unroll
            for (int nt2 = 0; nt2 < 4; nt2++) {
                const int row = wn + (2 * nt2 + (lm >> 1)) * 8 + lr;
                ldsm4(bF[nt2], tB + swzH(row, kb + (lm & 1) * 16));
            }
            const int cb = ks * 64 + tig * 8;       // fp32-tile byte col
            #pragma unroll
            for (int mt = 0; mt < 2; mt++) {
                const int r0 = wm + mt * 16 + g, r1 = r0 + 8;
                float2 v00 = *(const float2*)(baseA + swzF(r0, cb));
                float2 v10 = *(const float2*)(baseA + swzF(r1, cb));
                float2 v01 = *(const float2*)(baseA + swzF(r0, cb + 32));
                float2 v11 = *(const float2*)(baseA + swzF(r1, cb + 32));
                aF[mt][0] = f2h2(v00.x, v00.y);
                aF[mt][1] = f2h2(v10.x, v10.y);
                aF[mt][2] = f2h2(v01.x, v01.y);
                aF[mt][3] = f2h2(v11.x, v11.y);
            }
            #pragma unroll
            for (int mt = 0; mt < 2; mt++)
                #pragma unroll
                for (int nt2 = 0; nt2 < 4; nt2++) {
                    mma16816(acc[mt][2 * nt2],     aF[mt], &bF[nt2][0]);
                    mma16816(acc[mt][2 * nt2 + 1], aF[mt], &bF[nt2][2]);
                }
        }
        __syncthreads();
    }

    // ---- epilogue
    #pragma unroll
    for (int mt = 0; mt < 2; mt++) {
        const size_t r0 = (size_t)bm * 64 + wm + mt * 16 + g;
        #pragma unroll
        for (int nt = 0; nt < 8; nt++) {
            const int c0 = bn * 128 + wn + nt * 8 + tig * 2;
            const float bx = bias[c0], by = bias[c0 + 1];
            *(float2*)(C + r0 * N + c0) =
                make_float2(2048.0f * acc[mt][nt][0] + bx,
                            2048.0f * acc[mt][nt][1] + by);
            *(float2*)(C + (r0 + 8) * N + c0) =
                make_float2(2048.0f * acc[mt][nt][2] + bx,
                            2048.0f * acc[mt][nt][3] + by);
        }
    }
}

// ---------------------------------------------------------------------------
extern "C" void kernel_launch(void* const* d_in, const int* in_sizes, int n_in,
                              void* d_out, int out_size)
{
    const float* x  = (const float*)d_in[0];
    // d_in[1..5] = encoder_x, Wq, bq, Wk, bk -- mathematically dead
    const float* Wv = (const float*)d_in[6];
    const float* bv = (const float*)d_in[7];
    const float* Wo = (const float*)d_in[8];
    const float* bo = (const float*)d_in[9];
    float* out = (float*)d_out;

    __half* WcTh;
    float* t;
    cudaGetSymbolAddress((void**)&WcTh, g_WcTh);
    cudaGetSymbolAddress((void**)&t,    g_t);

    static int smem_set = 0;
    if (!smem_set) {
        cudaFuncSetAttribute(gemm1_w,
                             cudaFuncAttributeMaxDynamicSharedMemorySize, SM_G1);
        cudaFuncSetAttribute(gemm2_x,
                             cudaFuncAttributeMaxDynamicSharedMemorySize, SM_G2);
        smem_set = 1;
    }

    // 1) gemm1: WcT = Wo^T @ Wv^T  (256 CTAs) + 16 bias CTAs -> 272 CTAs
    {
        dim3 g(16, 17);   // y==16 -> bias CTAs
        gemm1_w<<<g, G1T, SM_G1>>>(Wo, Wv, WcTh, bv, bo, t);
    }

    // 2) gemm2: out = 2048 * x @ Wc + t  (1024 CTAs, 4 warps, 3 CTAs/SM)
    {
        dim3 g(8, 128);
        gemm2_x<<<g, G2T, SM_G2>>>(x, WcTh, out, t);
    }
}